// round 17
// baseline (speedup 1.0000x reference)
#include <cuda_runtime.h>
#include <cuda_bf16.h>

// PhyGate R16: champion (2 rows/thread, float2, scalar fast-math, 40 regs)
// with 64-thread blocks. R15 showed block-granularity is live: 256->128 thr
// gave ncu 16.22->15.46us. Testing the next step on the same axis.

struct Params {
    float dt, lin_w, lin_b;
    float p1, p2;
    float p3x, p3y, p3zg;   // p3z - 9.81 pre-folded
    float p5, p6;
    float k45;              // p4 * (1 + p5)
    float c15_over_r;       // 1.5 / r
};

__device__ __forceinline__ float fast_rcp(float x) {
    float y; asm("rcp.approx.f32 %0, %1;" : "=f"(y) : "f"(x)); return y;
}
__device__ __forceinline__ float fast_sqrt(float x) {
    float y; asm("sqrt.approx.f32 %0, %1;" : "=f"(y) : "f"(x)); return y;
}

__device__ __forceinline__ void phygate_row(
    float bb, float vx, float vy, float vz, float wx, float wy, float wz,
    const Params& P,
    float& ovx, float& ovy, float& ovz, float& owx, float& owy, float& owz)
{
    float z = fmaf(bb, P.lin_w, P.lin_b);
    float gate1 = fast_rcp(1.0f + __expf(-z));
    float gate2 = 1.0f - gate1;

    float r = P.p6;
    float t1 = vx - wy * r;
    float t2 = vy + wx * r;
    float inv = rsqrtf(fmaf(t1, t1, fmaf(t2, t2, 1e-6f)));
    float al = P.k45 * fabsf(vz) * inv;
    al = fminf(al, 0.4f);
    float oma = 1.0f - al;

    float vbx = fmaf(oma, vx, al * r * wy);
    float vby = fmaf(oma, vy, -(al * r) * wx);
    float vbz = -P.p5 * vz;

    float c = al * P.c15_over_r;
    float om15 = fmaf(-1.5f, al, 1.0f);
    float wbx = fmaf(-c, vy, om15 * wx);
    float wby = fmaf(c, vx, om15 * wy);
    float wbz = wz;

    float v2x = fmaf(gate1, vx, gate2 * vbx);
    float v2y = fmaf(gate1, vy, gate2 * vby);
    float v2z = fmaf(gate1, vz, gate2 * vbz);
    float w2x = fmaf(gate1, wx, gate2 * wbx);
    float w2y = fmaf(gate1, wy, gate2 * wby);
    float w2z = fmaf(gate1, wz, gate2 * wbz);

    float nv = fast_sqrt(fmaf(v2x, v2x, fmaf(v2y, v2y, v2z * v2z)));

    float cx = w2y * v2z - w2z * v2y;
    float cy = w2z * v2x - w2x * v2z;
    float cz = w2x * v2y - w2y * v2x;

    float k = -P.p1 * nv;
    float ax = fmaf(k, v2x, fmaf(P.p2, cx, P.p3x));
    float ay = fmaf(k, v2y, fmaf(P.p2, cy, P.p3y));
    float az = fmaf(k, v2z, fmaf(P.p2, cz, P.p3zg));

    ovx = fmaf(ax, P.dt, v2x);
    ovy = fmaf(ay, P.dt, v2y);
    ovz = fmaf(az, P.dt, v2z);
    owx = w2x; owy = w2y; owz = w2z;
}

__global__ void __launch_bounds__(64)
phygate_kernel(const float* __restrict__ b,
               const float* __restrict__ v,
               const float* __restrict__ w,
               const float* __restrict__ dt,
               const float* __restrict__ lin_w,
               const float* __restrict__ lin_b,
               const float* __restrict__ p1,
               const float* __restrict__ p2,
               const float* __restrict__ p3,
               const float* __restrict__ p4,
               const float* __restrict__ p5,
               const float* __restrict__ p6,
               float* __restrict__ out, int n)
{
    Params P;
    P.dt = __ldg(dt); P.lin_w = __ldg(lin_w); P.lin_b = __ldg(lin_b);
    P.p1 = __ldg(p1); P.p2 = __ldg(p2);
    P.p3x = __ldg(p3 + 0); P.p3y = __ldg(p3 + 1); P.p3zg = __ldg(p3 + 2) - 9.81f;
    float p4v = __ldg(p4);
    P.p5 = __ldg(p5); P.p6 = __ldg(p6);
    P.k45 = p4v * (1.0f + P.p5);
    P.c15_over_r = 1.5f / P.p6;

    int n2 = n >> 1;
    int t = blockIdx.x * blockDim.x + threadIdx.x;

    if (t < n2) {
        float2 b2 = reinterpret_cast<const float2*>(b)[t];
        const float2* v2p = reinterpret_cast<const float2*>(v) + 3 * t;
        const float2* w2p = reinterpret_cast<const float2*>(w) + 3 * t;
        float2 va = v2p[0], vb = v2p[1], vc = v2p[2];
        float2 wa = w2p[0], wb = w2p[1], wc = w2p[2];

        float ov0x, ov0y, ov0z, ow0x, ow0y, ow0z;
        float ov1x, ov1y, ov1z, ow1x, ow1y, ow1z;

        phygate_row(b2.x, va.x, va.y, vb.x, wa.x, wa.y, wb.x, P,
                    ov0x, ov0y, ov0z, ow0x, ow0y, ow0z);
        phygate_row(b2.y, vb.y, vc.x, vc.y, wb.y, wc.x, wc.y, P,
                    ov1x, ov1y, ov1z, ow1x, ow1y, ow1z);

        float2* outv = reinterpret_cast<float2*>(out) + 3 * t;
        float2* outw = reinterpret_cast<float2*>(out + 3 * (size_t)n) + 3 * t;
        outv[0] = make_float2(ov0x, ov0y);
        outv[1] = make_float2(ov0z, ov1x);
        outv[2] = make_float2(ov1y, ov1z);
        outw[0] = make_float2(ow0x, ow0y);
        outw[1] = make_float2(ow0z, ow1x);
        outw[2] = make_float2(ow1y, ow1z);
    }

    // Tail row if n is odd.
    if ((n & 1) && t == 0) {
        int row = n - 1;
        float ovx, ovy, ovz, owx, owy, owz;
        phygate_row(b[row], v[3*row], v[3*row+1], v[3*row+2],
                    w[3*row], w[3*row+1], w[3*row+2], P,
                    ovx, ovy, ovz, owx, owy, owz);
        out[3*row] = ovx; out[3*row+1] = ovy; out[3*row+2] = ovz;
        float* ow_base = out + 3 * (size_t)n;
        ow_base[3*row] = owx; ow_base[3*row+1] = owy; ow_base[3*row+2] = owz;
    }
}

extern "C" void kernel_launch(void* const* d_in, const int* in_sizes, int n_in,
                              void* d_out, int out_size)
{
    const float* b     = (const float*)d_in[0];
    const float* v     = (const float*)d_in[1];
    const float* w     = (const float*)d_in[2];
    const float* dt    = (const float*)d_in[3];
    const float* lin_w = (const float*)d_in[4];
    const float* lin_b = (const float*)d_in[5];
    const float* p1    = (const float*)d_in[6];
    const float* p2    = (const float*)d_in[7];
    const float* p3    = (const float*)d_in[8];
    const float* p4    = (const float*)d_in[9];
    const float* p5    = (const float*)d_in[10];
    const float* p6    = (const float*)d_in[11];

    int n = in_sizes[0];  // B rows
    int n2 = (n + 1) >> 1;
    int threads = 64;
    int blocks = (n2 + threads - 1) / threads;

    phygate_kernel<<<blocks, threads>>>(b, v, w, dt, lin_w, lin_b,
                                        p1, p2, p3, p4, p5, p6,
                                        (float*)d_out, n);
}